// round 12
// baseline (speedup 1.0000x reference)
#include <cuda_runtime.h>
#include <math.h>

#define NN 50000
#define EE 800000
#define DD 128

// ---------------- scratch (static __device__, no allocs) ----------------
__device__ float g_z[NN * DD];      // h @ W_func^T
__device__ float g_hs[NN * DD];     // h @ W_self^T
__device__ float g_ssrc[NN];
__device__ float g_sdst[NN];
__device__ float g_se[EE];          // per-edge attention dot
__device__ int   g_deg[NN];
__device__ int   g_cursor[NN];
__device__ int   g_off[NN + 1];
__device__ unsigned long long g_pair[EE];   // (logit<<32 | src) sorted by dst

// ---------------- helpers ----------------
__device__ __forceinline__ unsigned f2tf(float x) {
    unsigned r;
    asm("cvt.rna.tf32.f32 %0, %1;" : "=r"(r) : "f"(x));
    return r;
}

__device__ __forceinline__ void mma_tf32(float* c, unsigned a0, unsigned a1,
                                         unsigned a2, unsigned a3,
                                         unsigned b0, unsigned b1) {
    asm volatile(
        "mma.sync.aligned.m16n8k8.row.col.f32.tf32.tf32.f32 "
        "{%0,%1,%2,%3},{%4,%5,%6,%7},{%8,%9},{%0,%1,%2,%3};\n"
        : "+f"(c[0]), "+f"(c[1]), "+f"(c[2]), "+f"(c[3])
        : "r"(a0), "r"(a1), "r"(a2), "r"(a3), "r"(b0), "r"(b1));
}

__device__ __forceinline__ float warp_sum(float v) {
    #pragma unroll
    for (int o = 16; o; o >>= 1) v += __shfl_xor_sync(0xFFFFFFFFu, v, o);
    return v;
}

// ---------------- degree histogram (dst only) ----------------
__global__ void k_deg(const int* __restrict__ dst, int E) {
    int e = blockIdx.x * blockDim.x + threadIdx.x;
    if (e < E) atomicAdd(&g_deg[dst[e]], 1);
}

// ---------------- fast single-block scan: per-thread contiguous chunks ----------------
__global__ __launch_bounds__(1024) void k_scan_fast(int N) {
    __shared__ int wsum[32];
    int tid = threadIdx.x;
    int lane = tid & 31, w = tid >> 5;
    int C = (N + 1023) >> 10;                 // elements per thread
    int lo = tid * C;
    int hi = lo + C; if (hi > N) hi = N;

    int s = 0;
    for (int i = lo; i < hi; i++) s += g_deg[i];

    int x = s;
    #pragma unroll
    for (int o = 1; o < 32; o <<= 1) {
        int t = __shfl_up_sync(0xFFFFFFFFu, x, o);
        if (lane >= o) x += t;
    }
    if (lane == 31) wsum[w] = x;
    __syncthreads();
    if (w == 0) {
        int y = wsum[lane];
        #pragma unroll
        for (int o = 1; o < 32; o <<= 1) {
            int t = __shfl_up_sync(0xFFFFFFFFu, y, o);
            if (lane >= o) y += t;
        }
        wsum[lane] = y;
    }
    __syncthreads();

    int run = ((w == 0) ? 0 : wsum[w - 1]) + x - s;  // exclusive prefix
    for (int i = lo; i < hi; i++) {
        g_off[i] = run;
        g_cursor[i] = run;
        run += g_deg[i];
    }
    if (tid == 1023) g_off[N] = run;          // run == grand total here
}

// ---------------- dual tf32 GEMM (h_s and z) + fused rowdots ----------------
// W staged in smem with (b0,b1) fragment words ADJACENT -> uint2 LDS (halved LDS count)
__global__ __launch_bounds__(256, 1) void k_gemm_dual(
    const float* __restrict__ h, const float* __restrict__ Ws,
    const float* __restrict__ Wf, const float* __restrict__ Watt, int N) {
    extern __shared__ float smem[];
    float* sH = smem;                                  // 128*132 f32
    unsigned* sW = (unsigned*)(smem + 128 * 132);      // 128*136 tf32 bits (paired layout)

    int tid = threadIdx.x;
    int lane = tid & 31, w = tid >> 5;
    int tg = lane & 3, gid = lane >> 2;
    int row0 = blockIdx.x * 128;

    for (int i = tid; i < 128 * 32; i += 256) {
        int r = i >> 5, c4 = i & 31;
        float4 v = make_float4(0.f, 0.f, 0.f, 0.f);
        if (row0 + r < N) v = ((const float4*)h)[(size_t)(row0 + r) * 32 + c4];
        *(float4*)&sH[r * 132 + c4 * 4] = v;
    }
    __syncthreads();

    unsigned a[2][32];
    int ar0 = w * 16 + gid;
    #pragma unroll
    for (int j = 0; j < 32; j++) {
        a[0][j] = f2tf(sH[ar0 * 132 + tg + 4 * j]);
        a[1][j] = f2tf(sH[(ar0 + 8) * 132 + tg + 4 * j]);
    }

    const float* Wm[2] = {Ws, Wf};
    float* Om[2] = {g_hs, g_z};

    for (int m = 0; m < 2; m++) {
        __syncthreads();
        const float* W = Wm[m];
        // paired staging: sW[r*136 + kt*8 + tg2*2 + hi] = W[r][kt*8 + tg2 + 4*hi]
        for (int i = tid; i < 128 * 128; i += 256) {
            int r = i >> 7, c = i & 127;
            int kt = c >> 3, within = c & 7;
            int tg2 = within & 3, hi = within >> 2;
            sW[r * 136 + kt * 8 + tg2 * 2 + hi] = f2tf(W[i]);
        }
        __syncthreads();

        float acc[16][4];
        #pragma unroll
        for (int nt = 0; nt < 16; nt++)
            #pragma unroll
            for (int q = 0; q < 4; q++) acc[nt][q] = 0.f;

        #pragma unroll
        for (int kt = 0; kt < 16; kt++) {
            unsigned a0 = a[0][2 * kt], a2 = a[0][2 * kt + 1];
            unsigned a1 = a[1][2 * kt], a3 = a[1][2 * kt + 1];
            #pragma unroll
            for (int nt = 0; nt < 16; nt++) {
                uint2 b = *(const uint2*)&sW[(nt * 8 + gid) * 136 + kt * 8 + tg * 2];
                mma_tf32(acc[nt], a0, a1, a2, a3, b.x, b.y);
            }
        }

        float* O = Om[m];
        int r1 = row0 + ar0;
        int r2 = r1 + 8;
        #pragma unroll
        for (int nt = 0; nt < 16; nt++) {
            int col = nt * 8 + tg * 2;
            if (r1 < N) *(float2*)&O[(size_t)r1 * 128 + col] = make_float2(acc[nt][0], acc[nt][1]);
            if (r2 < N) *(float2*)&O[(size_t)r2 * 128 + col] = make_float2(acc[nt][2], acc[nt][3]);
        }

        if (m == 1) {
            float p1a = 0.f, p1b = 0.f, p2a = 0.f, p2b = 0.f;
            #pragma unroll
            for (int nt = 0; nt < 16; nt++) {
                int c0 = nt * 8 + tg * 2;
                float wa0 = Watt[c0],        wa1 = Watt[c0 + 1];
                float wb0 = Watt[128 + c0],  wb1 = Watt[128 + c0 + 1];
                p1a += acc[nt][0] * wa0 + acc[nt][1] * wa1;
                p1b += acc[nt][0] * wb0 + acc[nt][1] * wb1;
                p2a += acc[nt][2] * wa0 + acc[nt][3] * wa1;
                p2b += acc[nt][2] * wb0 + acc[nt][3] * wb1;
            }
            #pragma unroll
            for (int o = 1; o < 4; o <<= 1) {
                p1a += __shfl_xor_sync(0xFFFFFFFFu, p1a, o);
                p1b += __shfl_xor_sync(0xFFFFFFFFu, p1b, o);
                p2a += __shfl_xor_sync(0xFFFFFFFFu, p2a, o);
                p2b += __shfl_xor_sync(0xFFFFFFFFu, p2b, o);
            }
            if (tg == 0) {
                if (r1 < N) { g_ssrc[r1] = p1a; g_sdst[r1] = p1b; }
                if (r2 < N) { g_ssrc[r2] = p2a; g_sdst[r2] = p2b; }
            }
        }
    }
}

// ---------------- edge pre-dot: s_e = edge_w . wa[256:384]  (16 edges/warp) ----------------
__global__ __launch_bounds__(256) void k_edge_se(const float* __restrict__ ew,
                                                 const float* __restrict__ Watt, int E) {
    int wid = (blockIdx.x * blockDim.x + threadIdx.x) >> 5;
    int lane = threadIdx.x & 31;
    int base = wid * 16;
    if (base >= E) return;

    float4 w4 = ((const float4*)Watt)[64 + lane];   // wa[256:384]

    float s[16];
    #pragma unroll
    for (int j = 0; j < 16; j++) {
        float4 e4 = make_float4(0.f, 0.f, 0.f, 0.f);
        if (base + j < E) e4 = ((const float4*)ew)[(size_t)(base + j) * 32 + lane];
        s[j] = e4.x * w4.x + e4.y * w4.y + e4.z * w4.z + e4.w * w4.w;
    }

    #pragma unroll
    for (int o = 16; o; o >>= 1) {
        #pragma unroll
        for (int j = 0; j < 16; j++)
            s[j] += __shfl_xor_sync(0xFFFFFFFFu, s[j], o);
    }

    if (lane < 16) {
        int e = base + lane;
        if (e < E) {
            float se = s[0];
            #pragma unroll
            for (int j = 1; j < 16; j++)
                if (lane == j) se = s[j];
            g_se[e] = se;
        }
    }
}

// ---------------- edge final: logit + dst-sorted scatter ----------------
__global__ void k_edge_final(const int* __restrict__ src,
                             const int* __restrict__ dst, int E) {
    int e = blockIdx.x * blockDim.x + threadIdx.x;
    if (e >= E) return;
    int d = dst[e];
    int sc = src[e];
    float l = g_ssrc[sc] + g_sdst[d] + g_se[e];
    l = l > 0.f ? l : 0.01f * l;
    int p = atomicAdd(&g_cursor[d], 1);
    g_pair[p] = ((unsigned long long)__float_as_uint(l) << 32) | (unsigned)sc;
}

// ---------------- per-dst softmax + weighted gather + epilogue ----------------
__global__ __launch_bounds__(256, 3) void k_aggregate(const float* __restrict__ h,
                                                      float* __restrict__ out, int N) {
    __shared__ float swl[8][32];
    __shared__ int   ssv[8][32];
    int w = threadIdx.x >> 5;
    int lane = threadIdx.x & 31;
    int wid = (blockIdx.x * blockDim.x + threadIdx.x) >> 5;
    if (wid >= N) return;

    int beg = g_off[wid], end = g_off[wid + 1];
    int deg = end - beg;
    float4 hv = ((const float4*)h)[(size_t)wid * 32 + lane];
    float4 res;

    if (deg == 0) {
        res.x = hv.x + fmaxf(hv.x, 0.f);
        res.y = hv.y + fmaxf(hv.y, 0.f);
        res.z = hv.z + fmaxf(hv.z, 0.f);
        res.w = hv.w + fmaxf(hv.w, 0.f);
    } else {
        float4 acc = make_float4(0.f, 0.f, 0.f, 0.f);
        float denom = 0.f;

        if (deg <= 32) {
            unsigned long long u = 0;
            float lg = -INFINITY;
            if (lane < deg) {
                u = g_pair[beg + lane];
                lg = __uint_as_float((unsigned)(u >> 32));
            }
            float m = lg;
            #pragma unroll
            for (int o = 16; o; o >>= 1)
                m = fmaxf(m, __shfl_xor_sync(0xFFFFFFFFu, m, o));
            float wl = (lane < deg) ? __expf(lg - m) : 0.f;
            denom = wl;
            swl[w][lane] = wl;
            ssv[w][lane] = (int)(unsigned)u;
            __syncwarp();

            int k = 0;
            for (; k + 8 <= deg; k += 8) {
                float4 zb[8];
                #pragma unroll
                for (int j = 0; j < 8; j++) {
                    int aj = ssv[w][k + j];
                    zb[j] = ((const float4*)g_z)[(size_t)aj * 32 + lane];
                }
                #pragma unroll
                for (int j = 0; j < 8; j++) {
                    float wk = swl[w][k + j];
                    acc.x += wk * zb[j].x;
                    acc.y += wk * zb[j].y;
                    acc.z += wk * zb[j].z;
                    acc.w += wk * zb[j].w;
                }
            }
            for (; k < deg; k++) {
                float wk = swl[w][k];
                int   ak = ssv[w][k];
                float4 z0 = ((const float4*)g_z)[(size_t)ak * 32 + lane];
                acc.x += wk * z0.x;
                acc.y += wk * z0.y;
                acc.z += wk * z0.z;
                acc.w += wk * z0.w;
            }
        } else {
            float m = -INFINITY;
            for (int i = beg + lane; i < end; i += 32)
                m = fmaxf(m, __uint_as_float((unsigned)(g_pair[i] >> 32)));
            #pragma unroll
            for (int o = 16; o; o >>= 1)
                m = fmaxf(m, __shfl_xor_sync(0xFFFFFFFFu, m, o));

            for (int i = beg; i < end; i++) {
                unsigned long long u = g_pair[i];
                float wl = __expf(__uint_as_float((unsigned)(u >> 32)) - m);
                int   sv = (int)(unsigned)u;
                if (lane == 0) denom += wl;
                float4 z0 = ((const float4*)g_z)[(size_t)sv * 32 + lane];
                acc.x += wl * z0.x;
                acc.y += wl * z0.y;
                acc.z += wl * z0.z;
                acc.w += wl * z0.w;
            }
        }

        denom = warp_sum(denom);
        float inv = 1.f / fmaxf(denom, 1e-9f);
        float4 hs = ((const float4*)g_hs)[(size_t)wid * 32 + lane];
        float tx = hs.x + acc.x * inv;
        float ty = hs.y + acc.y * inv;
        float tz = hs.z + acc.z * inv;
        float tw = hs.w + acc.w * inv;
        res.x = hv.x + fmaxf(tx, 0.f);
        res.y = hv.y + fmaxf(ty, 0.f);
        res.z = hv.z + fmaxf(tz, 0.f);
        res.w = hv.w + fmaxf(tw, 0.f);
    }
    ((float4*)out)[(size_t)wid * 32 + lane] = res;
}

// ---------------- launch (fork/join; ncu lands on launch #4 = gemm) ----------------
extern "C" void kernel_launch(void* const* d_in, const int* in_sizes, int n_in,
                              void* d_out, int out_size) {
    const float* h    = (const float*)d_in[0];
    const float* ew   = (const float*)d_in[1];
    const float* Ws   = (const float*)d_in[2];
    const float* Wf   = (const float*)d_in[3];
    const float* Watt = (const float*)d_in[4];
    const int*   src  = (const int*)d_in[5];
    const int*   dst  = (const int*)d_in[6];
    float* out = (float*)d_out;

    int N = in_sizes[0] / DD;
    int E = in_sizes[5];

    const size_t gemm_smem = (size_t)(128 * 132 + 128 * 136) * 4;

    static cudaStream_t sA = nullptr, sB = nullptr;
    static cudaEvent_t evFork = nullptr, evA = nullptr, evB = nullptr;
    if (sA == nullptr) {
        cudaStreamCreateWithFlags(&sA, cudaStreamNonBlocking);
        cudaStreamCreateWithFlags(&sB, cudaStreamNonBlocking);
        cudaEventCreateWithFlags(&evFork, cudaEventDisableTiming);
        cudaEventCreateWithFlags(&evA, cudaEventDisableTiming);
        cudaEventCreateWithFlags(&evB, cudaEventDisableTiming);
        cudaFuncSetAttribute(k_gemm_dual,
                             cudaFuncAttributeMaxDynamicSharedMemorySize,
                             (int)gemm_smem);
    }

    // fork
    cudaEventRecord(evFork, 0);
    cudaStreamWaitEvent(sA, evFork, 0);
    cudaStreamWaitEvent(sB, evFork, 0);

    // launch #1 (stream A): 410MB edge_w stream
    int ewarps = (E + 15) / 16;
    k_edge_se<<<(ewarps + 7) / 8, 256, 0, sA>>>(ew, Watt, E);
    cudaEventRecord(evA, sA);

    // main stream: memset + deg (#2) + fast scan (#3)
    void* degp = nullptr;
    cudaGetSymbolAddress(&degp, g_deg);
    cudaMemsetAsync(degp, 0, (size_t)N * sizeof(int), 0);
    k_deg<<<(E + 255) / 256, 256>>>(dst, E);
    k_scan_fast<<<1, 1024>>>(N);

    // launch #4 (stream B): the GEMM  <-- ncu profiles this one
    k_gemm_dual<<<(N + 127) / 128, 256, gemm_smem, sB>>>(h, Ws, Wf, Watt, N);
    cudaEventRecord(evB, sB);

    // join
    cudaStreamWaitEvent(0, evA, 0);
    cudaStreamWaitEvent(0, evB, 0);

    // launch #5, #6
    k_edge_final<<<(E + 255) / 256, 256>>>(src, dst, E);
    k_aggregate<<<(N + 7) / 8, 256>>>(h, out, N);
}

// round 13
// speedup vs baseline: 1.0838x; 1.0838x over previous
#include <cuda_runtime.h>
#include <math.h>

#define NN 50000
#define EE 800000
#define DD 128

// ---------------- scratch (static __device__, no allocs) ----------------
__device__ float g_z[NN * DD];      // h @ W_func^T
__device__ float g_hs[NN * DD];     // h @ W_self^T
__device__ float g_ssrc[NN];        // z . wa[0:128]   (atomic-accumulated)
__device__ float g_sdst[NN];        // z . wa[128:256] (atomic-accumulated)
__device__ float g_se[EE];          // edge_w . wa[256:384]
__device__ int   g_deg[NN];
__device__ int   g_cursor[NN];
__device__ int   g_off[NN + 1];
__device__ unsigned long long g_pair[EE];   // (src<<32 | edge_id) sorted by dst

// ---------------- helpers ----------------
__device__ __forceinline__ unsigned f2tf(float x) {
    unsigned r;
    asm("cvt.rna.tf32.f32 %0, %1;" : "=r"(r) : "f"(x));
    return r;
}

__device__ __forceinline__ void mma_tf32(float* c, unsigned a0, unsigned a1,
                                         unsigned a2, unsigned a3,
                                         unsigned b0, unsigned b1) {
    asm volatile(
        "mma.sync.aligned.m16n8k8.row.col.f32.tf32.tf32.f32 "
        "{%0,%1,%2,%3},{%4,%5,%6,%7},{%8,%9},{%0,%1,%2,%3};\n"
        : "+f"(c[0]), "+f"(c[1]), "+f"(c[2]), "+f"(c[3])
        : "r"(a0), "r"(a1), "r"(a2), "r"(a3), "r"(b0), "r"(b1));
}

__device__ __forceinline__ float warp_sum(float v) {
    #pragma unroll
    for (int o = 16; o; o >>= 1) v += __shfl_xor_sync(0xFFFFFFFFu, v, o);
    return v;
}

// ---------------- degree histogram ----------------
__global__ void k_deg(const int* __restrict__ dst, int E) {
    int e = blockIdx.x * blockDim.x + threadIdx.x;
    if (e < E) atomicAdd(&g_deg[dst[e]], 1);
}

// ---------------- fast single-block scan ----------------
__global__ __launch_bounds__(1024) void k_scan_fast(int N) {
    __shared__ int wsum[32];
    int tid = threadIdx.x;
    int lane = tid & 31, w = tid >> 5;
    int C = (N + 1023) >> 10;
    int lo = tid * C;
    int hi = lo + C; if (hi > N) hi = N;

    int s = 0;
    for (int i = lo; i < hi; i++) s += g_deg[i];

    int x = s;
    #pragma unroll
    for (int o = 1; o < 32; o <<= 1) {
        int t = __shfl_up_sync(0xFFFFFFFFu, x, o);
        if (lane >= o) x += t;
    }
    if (lane == 31) wsum[w] = x;
    __syncthreads();
    if (w == 0) {
        int y = wsum[lane];
        #pragma unroll
        for (int o = 1; o < 32; o <<= 1) {
            int t = __shfl_up_sync(0xFFFFFFFFu, y, o);
            if (lane >= o) y += t;
        }
        wsum[lane] = y;
    }
    __syncthreads();

    int run = ((w == 0) ? 0 : wsum[w - 1]) + x - s;
    for (int i = lo; i < hi; i++) {
        g_off[i] = run;
        g_cursor[i] = run;
        run += g_deg[i];
    }
    if (tid == 1023) g_off[N] = run;
}

// ---------------- counting-sort scatter: (src, edge_id) by dst ----------------
__global__ void k_scatter0(const int* __restrict__ dst,
                           const int* __restrict__ src, int E) {
    int e = blockIdx.x * blockDim.x + threadIdx.x;
    if (e >= E) return;
    int d = dst[e];
    int p = atomicAdd(&g_cursor[d], 1);
    g_pair[p] = ((unsigned long long)(unsigned)src[e] << 32) | (unsigned)e;
}

// ---------------- dual tf32 GEMM: 512 threads, warp tile 16x64 ----------------
__global__ __launch_bounds__(512, 1) void k_gemm_dual(
    const float* __restrict__ h, const float* __restrict__ Ws,
    const float* __restrict__ Wf, const float* __restrict__ Watt, int N) {
    extern __shared__ unsigned smem[];
    unsigned* sHp = smem;                 // 128 x 136 paired tf32 of A tile
    unsigned* sW  = smem + 128 * 136;     // 128 x 136 paired tf32 of W

    int tid = threadIdx.x;
    int lane = tid & 31, wid = tid >> 5;
    int tg = lane & 3, gid = lane >> 2;
    int wm = wid & 7;                     // m slot 0-7  (16 rows each)
    int wn = wid >> 3;                    // n slot 0-1  (64 cols each)
    int row0 = blockIdx.x * 128;

    // stage A tile paired: sHp[r*136 + kt*8 + tg2*2 + hi] = tf32(A[r][kt*8+tg2+4*hi])
    for (int i = tid; i < 128 * 128; i += 512) {
        int r = i >> 7, c = i & 127;
        int kt = c >> 3, within = c & 7;
        int tg2 = within & 3, hi = within >> 2;
        float v = (row0 + r < N) ? h[(size_t)(row0 + r) * 128 + c] : 0.f;
        sHp[r * 136 + kt * 8 + tg2 * 2 + hi] = f2tf(v);
    }

    const float* Wm2[2] = {Ws, Wf};
    float* Om[2] = {g_hs, g_z};

    int r1 = row0 + wm * 16 + gid;
    int r2 = r1 + 8;
    int aoff1 = (wm * 16 + gid) * 136;
    int aoff2 = aoff1 + 8 * 136;

    for (int m = 0; m < 2; m++) {
        __syncthreads();
        const float* W = Wm2[m];
        for (int i = tid; i < 128 * 128; i += 512) {
            int r = i >> 7, c = i & 127;
            int kt = c >> 3, within = c & 7;
            int tg2 = within & 3, hi = within >> 2;
            sW[r * 136 + kt * 8 + tg2 * 2 + hi] = f2tf(W[i]);
        }
        __syncthreads();

        float acc[8][4];
        #pragma unroll
        for (int nt = 0; nt < 8; nt++)
            #pragma unroll
            for (int q = 0; q < 4; q++) acc[nt][q] = 0.f;

        #pragma unroll
        for (int kt = 0; kt < 16; kt++) {
            int ko = kt * 8 + tg * 2;
            uint2 aA = *(const uint2*)&sHp[aoff1 + ko];   // A[r1][kt*8+tg], A[r1][kt*8+tg+4]
            uint2 aB = *(const uint2*)&sHp[aoff2 + ko];   // A[r2][...]
            #pragma unroll
            for (int nt = 0; nt < 8; nt++) {
                uint2 b = *(const uint2*)&sW[(wn * 64 + nt * 8 + gid) * 136 + ko];
                mma_tf32(acc[nt], aA.x, aB.x, aA.y, aB.y, b.x, b.y);
            }
        }

        float* O = Om[m];
        #pragma unroll
        for (int nt = 0; nt < 8; nt++) {
            int col = wn * 64 + nt * 8 + tg * 2;
            if (r1 < N) *(float2*)&O[(size_t)r1 * 128 + col] = make_float2(acc[nt][0], acc[nt][1]);
            if (r2 < N) *(float2*)&O[(size_t)r2 * 128 + col] = make_float2(acc[nt][2], acc[nt][3]);
        }

        if (m == 1) {
            // partial rowdots over this warp's 64 cols; atomic-accumulate
            float p1a = 0.f, p1b = 0.f, p2a = 0.f, p2b = 0.f;
            #pragma unroll
            for (int nt = 0; nt < 8; nt++) {
                int c0 = wn * 64 + nt * 8 + tg * 2;
                float wa0 = Watt[c0],        wa1 = Watt[c0 + 1];
                float wb0 = Watt[128 + c0],  wb1 = Watt[128 + c0 + 1];
                p1a += acc[nt][0] * wa0 + acc[nt][1] * wa1;
                p1b += acc[nt][0] * wb0 + acc[nt][1] * wb1;
                p2a += acc[nt][2] * wa0 + acc[nt][3] * wa1;
                p2b += acc[nt][2] * wb0 + acc[nt][3] * wb1;
            }
            #pragma unroll
            for (int o = 1; o < 4; o <<= 1) {
                p1a += __shfl_xor_sync(0xFFFFFFFFu, p1a, o);
                p1b += __shfl_xor_sync(0xFFFFFFFFu, p1b, o);
                p2a += __shfl_xor_sync(0xFFFFFFFFu, p2a, o);
                p2b += __shfl_xor_sync(0xFFFFFFFFu, p2b, o);
            }
            if (tg == 0) {
                if (r1 < N) { atomicAdd(&g_ssrc[r1], p1a); atomicAdd(&g_sdst[r1], p1b); }
                if (r2 < N) { atomicAdd(&g_ssrc[r2], p2a); atomicAdd(&g_sdst[r2], p2b); }
            }
        }
    }
}

// ---------------- edge pre-dot: s_e = edge_w . wa[256:384]  (16 edges/warp) ----------------
__global__ __launch_bounds__(256) void k_edge_se(const float* __restrict__ ew,
                                                 const float* __restrict__ Watt, int E) {
    int wid = (blockIdx.x * blockDim.x + threadIdx.x) >> 5;
    int lane = threadIdx.x & 31;
    int base = wid * 16;
    if (base >= E) return;

    float4 w4 = ((const float4*)Watt)[64 + lane];

    float s[16];
    #pragma unroll
    for (int j = 0; j < 16; j++) {
        float4 e4 = make_float4(0.f, 0.f, 0.f, 0.f);
        if (base + j < E) e4 = ((const float4*)ew)[(size_t)(base + j) * 32 + lane];
        s[j] = e4.x * w4.x + e4.y * w4.y + e4.z * w4.z + e4.w * w4.w;
    }

    #pragma unroll
    for (int o = 16; o; o >>= 1) {
        #pragma unroll
        for (int j = 0; j < 16; j++)
            s[j] += __shfl_xor_sync(0xFFFFFFFFu, s[j], o);
    }

    if (lane < 16) {
        int e = base + lane;
        if (e < E) {
            float se = s[0];
            #pragma unroll
            for (int j = 1; j < 16; j++)
                if (lane == j) se = s[j];
            g_se[e] = se;
        }
    }
}

// ---------------- per-dst: inline logit + softmax + weighted gather + epilogue ----------------
__global__ __launch_bounds__(256, 3) void k_aggregate(const float* __restrict__ h,
                                                      float* __restrict__ out, int N) {
    __shared__ float swl[8][32];
    __shared__ int   ssv[8][32];
    int w = threadIdx.x >> 5;
    int lane = threadIdx.x & 31;
    int wid = (blockIdx.x * blockDim.x + threadIdx.x) >> 5;
    if (wid >= N) return;

    int beg = g_off[wid], end = g_off[wid + 1];
    int deg = end - beg;
    float4 hv = ((const float4*)h)[(size_t)wid * 32 + lane];
    float4 res;

    if (deg == 0) {
        res.x = hv.x + fmaxf(hv.x, 0.f);
        res.y = hv.y + fmaxf(hv.y, 0.f);
        res.z = hv.z + fmaxf(hv.z, 0.f);
        res.w = hv.w + fmaxf(hv.w, 0.f);
    } else {
        float sdst_w = g_sdst[wid];
        float4 acc = make_float4(0.f, 0.f, 0.f, 0.f);
        float denom = 0.f;

        if (deg <= 32) {
            int sv = 0;
            float lg = -INFINITY;
            if (lane < deg) {
                unsigned long long u = g_pair[beg + lane];
                sv = (int)(u >> 32);
                int e = (int)(unsigned)u;
                float l = g_ssrc[sv] + sdst_w + g_se[e];
                lg = l > 0.f ? l : 0.01f * l;
            }
            float m = lg;
            #pragma unroll
            for (int o = 16; o; o >>= 1)
                m = fmaxf(m, __shfl_xor_sync(0xFFFFFFFFu, m, o));
            float wl = (lane < deg) ? __expf(lg - m) : 0.f;
            denom = wl;
            swl[w][lane] = wl;
            ssv[w][lane] = sv;
            __syncwarp();

            int k = 0;
            for (; k + 8 <= deg; k += 8) {
                float4 zb[8];
                #pragma unroll
                for (int j = 0; j < 8; j++) {
                    int aj = ssv[w][k + j];
                    zb[j] = ((const float4*)g_z)[(size_t)aj * 32 + lane];
                }
                #pragma unroll
                for (int j = 0; j < 8; j++) {
                    float wk = swl[w][k + j];
                    acc.x += wk * zb[j].x;
                    acc.y += wk * zb[j].y;
                    acc.z += wk * zb[j].z;
                    acc.w += wk * zb[j].w;
                }
            }
            for (; k < deg; k++) {
                float wk = swl[w][k];
                int   ak = ssv[w][k];
                float4 z0 = ((const float4*)g_z)[(size_t)ak * 32 + lane];
                acc.x += wk * z0.x;
                acc.y += wk * z0.y;
                acc.z += wk * z0.z;
                acc.w += wk * z0.w;
            }
        } else {
            // rare path (deg > 32): recompute logits in two passes
            float m = -INFINITY;
            for (int i = beg + lane; i < end; i += 32) {
                unsigned long long u = g_pair[i];
                float l = g_ssrc[(int)(u >> 32)] + sdst_w + g_se[(int)(unsigned)u];
                l = l > 0.f ? l : 0.01f * l;
                m = fmaxf(m, l);
            }
            #pragma unroll
            for (int o = 16; o; o >>= 1)
                m = fmaxf(m, __shfl_xor_sync(0xFFFFFFFFu, m, o));

            for (int i = beg; i < end; i += 32) {
                int cnt = end - i; if (cnt > 32) cnt = 32;
                float wl = 0.f;
                int sv = 0;
                if (lane < cnt) {
                    unsigned long long u = g_pair[i + lane];
                    sv = (int)(u >> 32);
                    float l = g_ssrc[sv] + sdst_w + g_se[(int)(unsigned)u];
                    l = l > 0.f ? l : 0.01f * l;
                    wl = __expf(l - m);
                }
                denom += wl;
                swl[w][lane] = wl;
                ssv[w][lane] = sv;
                __syncwarp();
                for (int k = 0; k < cnt; k++) {
                    float wk = swl[w][k];
                    int   ak = ssv[w][k];
                    float4 z0 = ((const float4*)g_z)[(size_t)ak * 32 + lane];
                    acc.x += wk * z0.x;
                    acc.y += wk * z0.y;
                    acc.z += wk * z0.z;
                    acc.w += wk * z0.w;
                }
                __syncwarp();
            }
        }

        denom = warp_sum(denom);
        float inv = 1.f / fmaxf(denom, 1e-9f);
        float4 hs = ((const float4*)g_hs)[(size_t)wid * 32 + lane];
        float tx = hs.x + acc.x * inv;
        float ty = hs.y + acc.y * inv;
        float tz = hs.z + acc.z * inv;
        float tw = hs.w + acc.w * inv;
        res.x = hv.x + fmaxf(tx, 0.f);
        res.y = hv.y + fmaxf(ty, 0.f);
        res.z = hv.z + fmaxf(tz, 0.f);
        res.w = hv.w + fmaxf(tw, 0.f);
    }
    ((float4*)out)[(size_t)wid * 32 + lane] = res;
}

// ---------------- launch (fork/join) ----------------
extern "C" void kernel_launch(void* const* d_in, const int* in_sizes, int n_in,
                              void* d_out, int out_size) {
    const float* h    = (const float*)d_in[0];
    const float* ew   = (const float*)d_in[1];
    const float* Ws   = (const float*)d_in[2];
    const float* Wf   = (const float*)d_in[3];
    const float* Watt = (const float*)d_in[4];
    const int*   src  = (const int*)d_in[5];
    const int*   dst  = (const int*)d_in[6];
    float* out = (float*)d_out;

    int N = in_sizes[0] / DD;
    int E = in_sizes[5];

    const size_t gemm_smem = (size_t)(128 * 136) * 2 * 4;   // 139 KB

    static cudaStream_t sA = nullptr, sB = nullptr;
    static cudaEvent_t evFork = nullptr, evA = nullptr, evB = nullptr;
    if (sA == nullptr) {
        cudaStreamCreateWithFlags(&sA, cudaStreamNonBlocking);
        cudaStreamCreateWithFlags(&sB, cudaStreamNonBlocking);
        cudaEventCreateWithFlags(&evFork, cudaEventDisableTiming);
        cudaEventCreateWithFlags(&evA, cudaEventDisableTiming);
        cudaEventCreateWithFlags(&evB, cudaEventDisableTiming);
        cudaFuncSetAttribute(k_gemm_dual,
                             cudaFuncAttributeMaxDynamicSharedMemorySize,
                             (int)gemm_smem);
    }

    // zero accumulators + degree BEFORE fork (gemm atomics depend on ssrc/sdst)
    void *degp = nullptr, *ssrcp = nullptr, *sdstp = nullptr;
    cudaGetSymbolAddress(&degp, g_deg);
    cudaGetSymbolAddress(&ssrcp, g_ssrc);
    cudaGetSymbolAddress(&sdstp, g_sdst);
    cudaMemsetAsync(degp, 0, (size_t)N * sizeof(int), 0);
    cudaMemsetAsync(ssrcp, 0, (size_t)N * sizeof(float), 0);
    cudaMemsetAsync(sdstp, 0, (size_t)N * sizeof(float), 0);

    // fork
    cudaEventRecord(evFork, 0);
    cudaStreamWaitEvent(sA, evFork, 0);
    cudaStreamWaitEvent(sB, evFork, 0);

    // stream A: 410MB edge_w stream
    int ewarps = (E + 15) / 16;
    k_edge_se<<<(ewarps + 7) / 8, 256, 0, sA>>>(ew, Watt, E);
    cudaEventRecord(evA, sA);

    // stream B: rebuilt GEMM (16 warps/CTA)
    k_gemm_dual<<<(N + 127) / 128, 512, gemm_smem, sB>>>(h, Ws, Wf, Watt, N);
    cudaEventRecord(evB, sB);

    // main stream: deg + scan + early (src,edge) counting sort — hidden under A/B
    k_deg<<<(E + 255) / 256, 256>>>(dst, E);
    k_scan_fast<<<1, 1024>>>(N);
    k_scatter0<<<(E + 255) / 256, 256>>>(dst, src, E);

    // join
    cudaStreamWaitEvent(0, evA, 0);
    cudaStreamWaitEvent(0, evB, 0);

    // single serial tail kernel
    k_aggregate<<<(N + 7) / 8, 256>>>(h, out, N);
}

// round 15
// speedup vs baseline: 1.3837x; 1.2767x over previous
#include <cuda_runtime.h>
#include <math.h>

#define NN 50000
#define EE 800000
#define DD 128

// ---------------- scratch (static __device__, no allocs) ----------------
__device__ float g_z[NN * DD];      // h @ W_func^T
__device__ float g_hs[NN * DD];     // h @ W_self^T
__device__ float g_ssrc[NN];        // z . wa[0:128]   (atomic-accumulated)
__device__ float g_sdst[NN];        // z . wa[128:256] (atomic-accumulated)
__device__ float g_se[EE];          // edge_w . wa[256:384]
__device__ int   g_deg[NN];
__device__ int   g_incl[NN];
__device__ int   g_bsum[64];
__device__ int   g_bbase[64];
__device__ int   g_cursor[NN];
__device__ int   g_off[NN + 1];
__device__ unsigned long long g_pair[EE];   // (src<<32 | edge_id) sorted by dst

// ---------------- helpers ----------------
__device__ __forceinline__ unsigned f2tf(float x) {
    unsigned r;
    asm("cvt.rna.tf32.f32 %0, %1;" : "=r"(r) : "f"(x));
    return r;
}

__device__ __forceinline__ void mma_tf32(float* c, unsigned a0, unsigned a1,
                                         unsigned a2, unsigned a3,
                                         unsigned b0, unsigned b1) {
    asm volatile(
        "mma.sync.aligned.m16n8k8.row.col.f32.tf32.tf32.f32 "
        "{%0,%1,%2,%3},{%4,%5,%6,%7},{%8,%9},{%0,%1,%2,%3};\n"
        : "+f"(c[0]), "+f"(c[1]), "+f"(c[2]), "+f"(c[3])
        : "r"(a0), "r"(a1), "r"(a2), "r"(a3), "r"(b0), "r"(b1));
}

__device__ __forceinline__ float warp_sum(float v) {
    #pragma unroll
    for (int o = 16; o; o >>= 1) v += __shfl_xor_sync(0xFFFFFFFFu, v, o);
    return v;
}

// ---------------- degree histogram ----------------
__global__ void k_deg(const int* __restrict__ dst, int E) {
    int e = blockIdx.x * blockDim.x + threadIdx.x;
    if (e < E) atomicAdd(&g_deg[dst[e]], 1);
}

// ---------------- multi-block scan (proven ~14us total) ----------------
__global__ void k_scan1(int N) {
    __shared__ int s[1024];
    int i = blockIdx.x * 1024 + threadIdx.x;
    int v = (i < N) ? g_deg[i] : 0;
    s[threadIdx.x] = v;
    #pragma unroll
    for (int off = 1; off < 1024; off <<= 1) {
        __syncthreads();
        int t = (threadIdx.x >= off) ? s[threadIdx.x - off] : 0;
        __syncthreads();
        s[threadIdx.x] += t;
    }
    if (i < N) g_incl[i] = s[threadIdx.x];
    if (threadIdx.x == 1023) g_bsum[blockIdx.x] = s[1023];
}

__global__ void k_scan2(int nb) {
    if (threadIdx.x == 0) {
        int base = 0;
        for (int b = 0; b < nb; b++) { g_bbase[b] = base; base += g_bsum[b]; }
    }
}

__global__ void k_scan3(int N) {
    int i = blockIdx.x * blockDim.x + threadIdx.x;
    if (i >= N) return;
    int start = g_incl[i] - g_deg[i] + g_bbase[i >> 10];
    g_off[i] = start;
    g_cursor[i] = start;
    if (i == N - 1) g_off[N] = start + g_deg[i];
}

// ---------------- counting-sort scatter: (src, edge_id) by dst ----------------
__global__ void k_scatter0(const int* __restrict__ dst,
                           const int* __restrict__ src, int E) {
    int e = blockIdx.x * blockDim.x + threadIdx.x;
    if (e >= E) return;
    int d = dst[e];
    int p = atomicAdd(&g_cursor[d], 1);
    g_pair[p] = ((unsigned long long)(unsigned)src[e] << 32) | (unsigned)e;
}

// ---------------- dual tf32 GEMM: 512 threads, warp tile 16x64 ----------------
__global__ __launch_bounds__(512, 1) void k_gemm_dual(
    const float* __restrict__ h, const float* __restrict__ Ws,
    const float* __restrict__ Wf, const float* __restrict__ Watt, int N) {
    extern __shared__ unsigned smem[];
    unsigned* sHp = smem;                 // 128 x 136 paired tf32 of A tile
    unsigned* sW  = smem + 128 * 136;     // 128 x 136 paired tf32 of W

    int tid = threadIdx.x;
    int lane = tid & 31, wid = tid >> 5;
    int tg = lane & 3, gid = lane >> 2;
    int wm = wid & 7;
    int wn = wid >> 3;
    int row0 = blockIdx.x * 128;

    for (int i = tid; i < 128 * 128; i += 512) {
        int r = i >> 7, c = i & 127;
        int kt = c >> 3, within = c & 7;
        int tg2 = within & 3, hi = within >> 2;
        float v = (row0 + r < N) ? h[(size_t)(row0 + r) * 128 + c] : 0.f;
        sHp[r * 136 + kt * 8 + tg2 * 2 + hi] = f2tf(v);
    }

    const float* Wm2[2] = {Ws, Wf};
    float* Om[2] = {g_hs, g_z};

    int r1 = row0 + wm * 16 + gid;
    int r2 = r1 + 8;
    int aoff1 = (wm * 16 + gid) * 136;
    int aoff2 = aoff1 + 8 * 136;

    for (int m = 0; m < 2; m++) {
        __syncthreads();
        const float* W = Wm2[m];
        for (int i = tid; i < 128 * 128; i += 512) {
            int r = i >> 7, c = i & 127;
            int kt = c >> 3, within = c & 7;
            int tg2 = within & 3, hi = within >> 2;
            sW[r * 136 + kt * 8 + tg2 * 2 + hi] = f2tf(W[i]);
        }
        __syncthreads();

        float acc[8][4];
        #pragma unroll
        for (int nt = 0; nt < 8; nt++)
            #pragma unroll
            for (int q = 0; q < 4; q++) acc[nt][q] = 0.f;

        #pragma unroll
        for (int kt = 0; kt < 16; kt++) {
            int ko = kt * 8 + tg * 2;
            uint2 aA = *(const uint2*)&sHp[aoff1 + ko];
            uint2 aB = *(const uint2*)&sHp[aoff2 + ko];
            #pragma unroll
            for (int nt = 0; nt < 8; nt++) {
                uint2 b = *(const uint2*)&sW[(wn * 64 + nt * 8 + gid) * 136 + ko];
                mma_tf32(acc[nt], aA.x, aB.x, aA.y, aB.y, b.x, b.y);
            }
        }

        float* O = Om[m];
        #pragma unroll
        for (int nt = 0; nt < 8; nt++) {
            int col = wn * 64 + nt * 8 + tg * 2;
            if (r1 < N) *(float2*)&O[(size_t)r1 * 128 + col] = make_float2(acc[nt][0], acc[nt][1]);
            if (r2 < N) *(float2*)&O[(size_t)r2 * 128 + col] = make_float2(acc[nt][2], acc[nt][3]);
        }

        if (m == 1) {
            float p1a = 0.f, p1b = 0.f, p2a = 0.f, p2b = 0.f;
            #pragma unroll
            for (int nt = 0; nt < 8; nt++) {
                int c0 = wn * 64 + nt * 8 + tg * 2;
                float wa0 = Watt[c0],        wa1 = Watt[c0 + 1];
                float wb0 = Watt[128 + c0],  wb1 = Watt[128 + c0 + 1];
                p1a += acc[nt][0] * wa0 + acc[nt][1] * wa1;
                p1b += acc[nt][0] * wb0 + acc[nt][1] * wb1;
                p2a += acc[nt][2] * wa0 + acc[nt][3] * wa1;
                p2b += acc[nt][2] * wb0 + acc[nt][3] * wb1;
            }
            #pragma unroll
            for (int o = 1; o < 4; o <<= 1) {
                p1a += __shfl_xor_sync(0xFFFFFFFFu, p1a, o);
                p1b += __shfl_xor_sync(0xFFFFFFFFu, p1b, o);
                p2a += __shfl_xor_sync(0xFFFFFFFFu, p2a, o);
                p2b += __shfl_xor_sync(0xFFFFFFFFu, p2b, o);
            }
            if (tg == 0) {
                if (r1 < N) { atomicAdd(&g_ssrc[r1], p1a); atomicAdd(&g_sdst[r1], p1b); }
                if (r2 < N) { atomicAdd(&g_ssrc[r2], p2a); atomicAdd(&g_sdst[r2], p2b); }
            }
        }
    }
}

// ---------------- edge pre-dot: s_e = edge_w . wa[256:384]  (16 edges/warp) ----------------
__global__ __launch_bounds__(256) void k_edge_se(const float* __restrict__ ew,
                                                 const float* __restrict__ Watt, int E) {
    int wid = (blockIdx.x * blockDim.x + threadIdx.x) >> 5;
    int lane = threadIdx.x & 31;
    int base = wid * 16;
    if (base >= E) return;

    float4 w4 = ((const float4*)Watt)[64 + lane];

    float s[16];
    #pragma unroll
    for (int j = 0; j < 16; j++) {
        float4 e4 = make_float4(0.f, 0.f, 0.f, 0.f);
        if (base + j < E) e4 = ((const float4*)ew)[(size_t)(base + j) * 32 + lane];
        s[j] = e4.x * w4.x + e4.y * w4.y + e4.z * w4.z + e4.w * w4.w;
    }

    #pragma unroll
    for (int o = 16; o; o >>= 1) {
        #pragma unroll
        for (int j = 0; j < 16; j++)
            s[j] += __shfl_xor_sync(0xFFFFFFFFu, s[j], o);
    }

    if (lane < 16) {
        int e = base + lane;
        if (e < E) {
            float se = s[0];
            #pragma unroll
            for (int j = 1; j < 16; j++)
                if (lane == j) se = s[j];
            g_se[e] = se;
        }
    }
}

// ---------------- per-dst: inline logit + softmax + weighted gather + epilogue ----------------
__global__ __launch_bounds__(256, 3) void k_aggregate(const float* __restrict__ h,
                                                      float* __restrict__ out, int N) {
    __shared__ float swl[8][32];
    __shared__ int   ssv[8][32];
    int w = threadIdx.x >> 5;
    int lane = threadIdx.x & 31;
    int wid = (blockIdx.x * blockDim.x + threadIdx.x) >> 5;
    if (wid >= N) return;

    int beg = g_off[wid], end = g_off[wid + 1];
    int deg = end - beg;
    float4 hv = ((const float4*)h)[(size_t)wid * 32 + lane];
    float4 res;

    if (deg == 0) {
        res.x = hv.x + fmaxf(hv.x, 0.f);
        res.y = hv.y + fmaxf(hv.y, 0.f);
        res.z = hv.z + fmaxf(hv.z, 0.f);
        res.w = hv.w + fmaxf(hv.w, 0.f);
    } else {
        float sdst_w = g_sdst[wid];
        float4 acc = make_float4(0.f, 0.f, 0.f, 0.f);
        float denom = 0.f;

        if (deg <= 32) {
            int sv = 0;
            float lg = -INFINITY;
            if (lane < deg) {
                unsigned long long u = g_pair[beg + lane];
                sv = (int)(u >> 32);
                int e = (int)(unsigned)u;
                float l = g_ssrc[sv] + sdst_w + g_se[e];
                lg = l > 0.f ? l : 0.01f * l;
            }
            float m = lg;
            #pragma unroll
            for (int o = 16; o; o >>= 1)
                m = fmaxf(m, __shfl_xor_sync(0xFFFFFFFFu, m, o));
            float wl = (lane < deg) ? __expf(lg - m) : 0.f;
            denom = wl;
            swl[w][lane] = wl;
            ssv[w][lane] = sv;
            __syncwarp();

            int k = 0;
            for (; k + 8 <= deg; k += 8) {
                float4 zb[8];
                #pragma unroll
                for (int j = 0; j < 8; j++) {
                    int aj = ssv[w][k + j];
                    zb[j] = ((const float4*)g_z)[(size_t)aj * 32 + lane];
                }
                #pragma unroll
                for (int j = 0; j < 8; j++) {
                    float wk = swl[w][k + j];
                    acc.x += wk * zb[j].x;
                    acc.y += wk * zb[j].y;
                    acc.z += wk * zb[j].z;
                    acc.w += wk * zb[j].w;
                }
            }
            for (; k < deg; k++) {
                float wk = swl[w][k];
                int   ak = ssv[w][k];
                float4 z0 = ((const float4*)g_z)[(size_t)ak * 32 + lane];
                acc.x += wk * z0.x;
                acc.y += wk * z0.y;
                acc.z += wk * z0.z;
                acc.w += wk * z0.w;
            }
        } else {
            float m = -INFINITY;
            for (int i = beg + lane; i < end; i += 32) {
                unsigned long long u = g_pair[i];
                float l = g_ssrc[(int)(u >> 32)] + sdst_w + g_se[(int)(unsigned)u];
                l = l > 0.f ? l : 0.01f * l;
                m = fmaxf(m, l);
            }
            #pragma unroll
            for (int o = 16; o; o >>= 1)
                m = fmaxf(m, __shfl_xor_sync(0xFFFFFFFFu, m, o));

            for (int i = beg; i < end; i += 32) {
                int cnt = end - i; if (cnt > 32) cnt = 32;
                float wl = 0.f;
                int sv = 0;
                if (lane < cnt) {
                    unsigned long long u = g_pair[i + lane];
                    sv = (int)(u >> 32);
                    float l = g_ssrc[sv] + sdst_w + g_se[(int)(unsigned)u];
                    l = l > 0.f ? l : 0.01f * l;
                    wl = __expf(l - m);
                }
                denom += wl;
                swl[w][lane] = wl;
                ssv[w][lane] = sv;
                __syncwarp();
                for (int k = 0; k < cnt; k++) {
                    float wk = swl[w][k];
                    int   ak = ssv[w][k];
                    float4 z0 = ((const float4*)g_z)[(size_t)ak * 32 + lane];
                    acc.x += wk * z0.x;
                    acc.y += wk * z0.y;
                    acc.z += wk * z0.z;
                    acc.w += wk * z0.w;
                }
                __syncwarp();
            }
        }

        denom = warp_sum(denom);
        float inv = 1.f / fmaxf(denom, 1e-9f);
        float4 hs = ((const float4*)g_hs)[(size_t)wid * 32 + lane];
        float tx = hs.x + acc.x * inv;
        float ty = hs.y + acc.y * inv;
        float tz = hs.z + acc.z * inv;
        float tw = hs.w + acc.w * inv;
        res.x = hv.x + fmaxf(tx, 0.f);
        res.y = hv.y + fmaxf(ty, 0.f);
        res.z = hv.z + fmaxf(tz, 0.f);
        res.w = hv.w + fmaxf(tw, 0.f);
    }
    ((float4*)out)[(size_t)wid * 32 + lane] = res;
}

// ---------------- launch (fork/join; launch #4 = gemm for ncu) ----------------
extern "C" void kernel_launch(void* const* d_in, const int* in_sizes, int n_in,
                              void* d_out, int out_size) {
    const float* h    = (const float*)d_in[0];
    const float* ew   = (const float*)d_in[1];
    const float* Ws   = (const float*)d_in[2];
    const float* Wf   = (const float*)d_in[3];
    const float* Watt = (const float*)d_in[4];
    const int*   src  = (const int*)d_in[5];
    const int*   dst  = (const int*)d_in[6];
    float* out = (float*)d_out;

    int N = in_sizes[0] / DD;
    int E = in_sizes[5];

    const size_t gemm_smem = (size_t)(128 * 136) * 2 * 4;   // ~139 KB

    static cudaStream_t sA = nullptr, sB = nullptr;
    static cudaEvent_t evFork = nullptr, evA = nullptr, evB = nullptr;
    if (sA == nullptr) {
        cudaStreamCreateWithFlags(&sA, cudaStreamNonBlocking);
        cudaStreamCreateWithFlags(&sB, cudaStreamNonBlocking);
        cudaEventCreateWithFlags(&evFork, cudaEventDisableTiming);
        cudaEventCreateWithFlags(&evA, cudaEventDisableTiming);
        cudaEventCreateWithFlags(&evB, cudaEventDisableTiming);
        cudaFuncSetAttribute(k_gemm_dual,
                             cudaFuncAttributeMaxDynamicSharedMemorySize,
                             (int)gemm_smem);
    }

    // zero accumulators + degree BEFORE fork
    void *degp = nullptr, *ssrcp = nullptr, *sdstp = nullptr;
    cudaGetSymbolAddress(&degp, g_deg);
    cudaGetSymbolAddress(&ssrcp, g_ssrc);
    cudaGetSymbolAddress(&sdstp, g_sdst);
    cudaMemsetAsync(degp, 0, (size_t)N * sizeof(int), 0);
    cudaMemsetAsync(ssrcp, 0, (size_t)N * sizeof(float), 0);
    cudaMemsetAsync(sdstp, 0, (size_t)N * sizeof(float), 0);

    // fork
    cudaEventRecord(evFork, 0);
    cudaStreamWaitEvent(sA, evFork, 0);
    cudaStreamWaitEvent(sB, evFork, 0);

    // #1 (stream A): 410MB edge_w stream
    int ewarps = (E + 15) / 16;
    k_edge_se<<<(ewarps + 7) / 8, 256, 0, sA>>>(ew, Watt, E);
    cudaEventRecord(evA, sA);

    // #2, #3 (main): deg + scan1
    k_deg<<<(E + 255) / 256, 256>>>(dst, E);
    int nb = (N + 1023) / 1024;
    k_scan1<<<nb, 1024>>>(N);

    // #4 (stream B): rebuilt GEMM  <-- ncu profiles this one
    k_gemm_dual<<<(N + 127) / 128, 512, gemm_smem, sB>>>(h, Ws, Wf, Watt, N);
    cudaEventRecord(evB, sB);

    // #5-#7 (main): scan2, scan3, scatter0
    k_scan2<<<1, 32>>>(nb);
    k_scan3<<<(N + 255) / 256, 256>>>(N);
    k_scatter0<<<(E + 255) / 256, 256>>>(dst, src, E);

    // join
    cudaStreamWaitEvent(0, evA, 0);
    cudaStreamWaitEvent(0, evB, 0);

    // #8: single serial tail kernel
    k_aggregate<<<(N + 7) / 8, 256>>>(h, out, N);
}